// round 14
// baseline (speedup 1.0000x reference)
#include <cuda_runtime.h>

#define HIDDEN 128
#define THREADS 128
#define NRAY 8    // rays per thread = 4 packed f32x2 pairs
#define NPAIR 4

typedef unsigned long long ull;

__device__ __forceinline__ float ex2f_(float x) {
    float y; asm("ex2.approx.f32 %0, %1;" : "=f"(y) : "f"(x)); return y;
}
__device__ __forceinline__ ull pk2(float lo, float hi) {
    ull r; asm("mov.b64 %0, {%1, %2};" : "=l"(r) : "f"(lo), "f"(hi)); return r;
}
__device__ __forceinline__ void upk2(ull v, float& lo, float& hi) {
    asm("mov.b64 {%0, %1}, %2;" : "=f"(lo), "=f"(hi) : "l"(v));
}
__device__ __forceinline__ ull ffma2(ull a, ull b, ull c) {
    ull d; asm("fma.rn.f32x2 %0, %1, %2, %3;" : "=l"(d) : "l"(a), "l"(b), "l"(c)); return d;
}
__device__ __forceinline__ ull fmul2(ull a, ull b) {
    ull d; asm("mul.rn.f32x2 %0, %1, %2;" : "=l"(d) : "l"(a), "l"(b)); return d;
}
__device__ __forceinline__ ull abs2_(ull a) {
    ull d; asm("and.b64 %0, %1, 0x7FFFFFFF7FFFFFFF;" : "=l"(d) : "l"(a)); return d;
}

// Degree-3 poly for ln(1+e), e in [0,1] (verified R7; max err ~5.1e-4,
// end-to-end rel_err ~1e-5). c0 folded into the global constant term.
#define PE0  0.0005089380f
#define PE1  0.9823484000f
#define PE2 -0.3970146000f
#define PE3  0.1076817600f

struct __align__(16) W48 {
    ull w0, w1, w2, b;    // W1 rows + b1, pre-scaled by log2(e), dup {w,w}
    ull w2p;              // {W2, W2}
    ull w2h;              // {W2*ln2/2, W2*ln2/2}
};

__global__ __launch_bounds__(THREADS, 5)
void raymarch_kernel(const float* __restrict__ r,
                     const float* __restrict__ pivot,
                     const float* __restrict__ W1,
                     const float* __restrict__ b1,
                     const float* __restrict__ W2,
                     const float* __restrict__ b2,
                     const int*   __restrict__ n_iter_p,
                     float* __restrict__ out,
                     int n_rays)
{
    __shared__ W48 s_w[HIDDEN];     // 6 KB
    __shared__ float s_lin[4];      // {vx/2, vy/2, vz/2, const term}

    const float L2E = 1.4426950408889634f;
    const float LN2 = 0.6931471805599453f;

    const int tid = threadIdx.x;
    {
        float a0 = W1[tid] * L2E;
        float a1 = W1[HIDDEN + tid] * L2E;
        float a2 = W1[2 * HIDDEN + tid] * L2E;
        float bb = b1[tid] * L2E;
        float w2 = W2[tid];
        s_w[tid].w0  = pk2(a0, a0);
        s_w[tid].w1  = pk2(a1, a1);
        s_w[tid].w2  = pk2(a2, a2);
        s_w[tid].b   = pk2(bb, bb);
        s_w[tid].w2p = pk2(w2, w2);
        float wh = w2 * (0.5f * LN2);
        s_w[tid].w2h = pk2(wh, wh);
    }
    // Warp 0: reduce v = sum_j W2_j*W1_j, cb = sum_j W2_j*b1_j, sw = sum W2_j.
    if (tid < 32) {
        float vx = 0.f, vy = 0.f, vz = 0.f, cb = 0.f, sw = 0.f;
        #pragma unroll
        for (int k = 0; k < 4; ++k) {
            int j = tid + 32 * k;
            float w2 = W2[j];
            vx = fmaf(w2, W1[j], vx);
            vy = fmaf(w2, W1[HIDDEN + j], vy);
            vz = fmaf(w2, W1[2 * HIDDEN + j], vz);
            cb = fmaf(w2, b1[j], cb);
            sw += w2;
        }
        #pragma unroll
        for (int o = 16; o > 0; o >>= 1) {
            vx += __shfl_xor_sync(0xFFFFFFFF, vx, o);
            vy += __shfl_xor_sync(0xFFFFFFFF, vy, o);
            vz += __shfl_xor_sync(0xFFFFFFFF, vz, o);
            cb += __shfl_xor_sync(0xFFFFFFFF, cb, o);
            sw += __shfl_xor_sync(0xFFFFFFFF, sw, o);
        }
        if (tid == 0) {
            s_lin[0] = 0.5f * vx;
            s_lin[1] = 0.5f * vy;
            s_lin[2] = 0.5f * vz;
            s_lin[3] = 0.5f * cb + b2[0] + PE0 * sw;
        }
    }
    __syncthreads();

    const float pv0 = pivot[0], pv1 = pivot[1], pv2 = pivot[2];
    const float lx = s_lin[0], ly = s_lin[1], lz = s_lin[2], lw = s_lin[3];
    // lin(alpha) = A + alpha * B_k  (exact refactor of lx*px+ly*py+lz*pz+lw)
    const float linA = fmaf(lx, pv0, fmaf(ly, pv1, fmaf(lz, pv2, lw)));
    const int n_it = n_iter_p ? *n_iter_p : 20;

    const int base = (blockIdx.x * THREADS + tid) * NRAY;
    const bool valid = (base + NRAY - 1 < n_rays);

    float rn0[NRAY], dx[NRAY], dy[NRAY], dz[NRAY], alpha[NRAY], linB[NRAY];
    #pragma unroll
    for (int k = 0; k < NRAY; ++k) {
        float4 rv = valid ? reinterpret_cast<const float4*>(r)[base + k]
                          : make_float4(1.f, 0.f, 0.f, 0.f);
        float inv = rsqrtf(rv.x * rv.x + rv.y * rv.y + rv.z * rv.z + rv.w * rv.w);
        rn0[k] = rv.x * inv;
        dx[k] = rv.y * inv;
        dy[k] = rv.z * inv;
        dz[k] = rv.w * inv;
        linB[k] = fmaf(lz, dz[k], fmaf(ly, dy[k], lx * dx[k]));
        alpha[k] = 0.f;
    }

    const ull C1 = pk2(PE1, PE1), C2 = pk2(PE2, PE2), C3 = pk2(PE3, PE3);

    for (int it = 0; it < n_it; ++it) {
        ull p0d[NPAIR], p1d[NPAIR], p2d[NPAIR], accP[NPAIR], accM[NPAIR];
        float lin[NRAY], x0[NRAY];

        #pragma unroll
        for (int q = 0; q < NPAIR; ++q) {
            const int k = 2 * q;
            p0d[q] = pk2(fmaf(alpha[k], dx[k], pv0), fmaf(alpha[k+1], dx[k+1], pv0));
            p1d[q] = pk2(fmaf(alpha[k], dy[k], pv1), fmaf(alpha[k+1], dy[k+1], pv1));
            p2d[q] = pk2(fmaf(alpha[k], dz[k], pv2), fmaf(alpha[k+1], dz[k+1], pv2));
            lin[k]   = fmaf(alpha[k],   linB[k],   linA);
            lin[k+1] = fmaf(alpha[k+1], linB[k+1], linA);
            x0[k]   = alpha[k]   * rn0[k];
            x0[k+1] = alpha[k+1] * rn0[k+1];
            accP[q] = 0ull;
            accM[q] = 0ull;
        }

        #pragma unroll 2
        for (int j = 0; j < HIDDEN; ++j) {
            ulonglong2 q0 = *reinterpret_cast<const ulonglong2*>(&s_w[j].w0);   // w0, w1
            ulonglong2 q1 = *reinterpret_cast<const ulonglong2*>(&s_w[j].w2);   // w2, b
            ulonglong2 q2 = *reinterpret_cast<const ulonglong2*>(&s_w[j].w2p);  // w2p, w2h

            #pragma unroll
            for (int q = 0; q < NPAIR; ++q) {
                // aL = (x . W1 + b1) * log2e, packed over 2 rays
                ull aL = ffma2(p0d[q], q0.x, ffma2(p1d[q], q0.y, ffma2(p2d[q], q1.x, q1.y)));
                ull ab = abs2_(aL);
                float alo, ahi; upk2(ab, alo, ahi);

                // e = 2^(-|aL|)
                float elo = ex2f_(-alo);
                float ehi = ex2f_(-ahi);
                ull e2 = pk2(elo, ehi);

                // ln(1+e) minus c0: Horner (c0 folded into linA)
                ull p = ffma2(C3, e2, C2);
                p = ffma2(p, e2, C1);
                ull t = fmul2(p, e2);

                accP[q] = ffma2(q2.x, t, accP[q]);   // W2 * (poly*e)
                accM[q] = ffma2(q2.y, ab, accM[q]);  // (W2*ln2/2) * |aL|
            }
        }

        #pragma unroll
        for (int q = 0; q < NPAIR; ++q) {
            const int k = 2 * q;
            float pl, ph, ml, mh;
            upk2(accP[q], pl, ph);
            upk2(accM[q], ml, mh);
            float s0 = (pl + ml) + lin[k];
            float s1 = (ph + mh) + lin[k+1];
            float a0 = fabsf(s0);
            float a1 = fabsf(s1);
            float ext0 = fmaxf(fmaxf(s0, x0[k]   - a0), -a0 - x0[k]);
            float ext1 = fmaxf(fmaxf(s1, x0[k+1] - a1), -a1 - x0[k+1]);
            alpha[k]   -= ext0;
            alpha[k+1] -= ext1;
        }
    }

    if (valid) {
        #pragma unroll
        for (int k = 0; k < NRAY; ++k) {
            const int i = base + k;
            out[3 * i + 0] = fmaf(alpha[k], dx[k], pv0);
            out[3 * i + 1] = fmaf(alpha[k], dy[k], pv1);
            out[3 * i + 2] = fmaf(alpha[k], dz[k], pv2);
        }
    }
}

extern "C" void kernel_launch(void* const* d_in, const int* in_sizes, int n_in,
                              void* d_out, int out_size)
{
    const float* r     = (const float*)d_in[0];
    const float* pivot = (const float*)d_in[1];
    const float* W1    = (const float*)d_in[2];
    const float* b1    = (const float*)d_in[3];
    const float* W2    = (const float*)d_in[4];
    const float* b2    = (const float*)d_in[5];
    const int*   n_it  = (n_in > 6) ? (const int*)d_in[6] : nullptr;

    const int n_rays = in_sizes[0] / 4;
    const int rays_per_block = THREADS * NRAY;
    const int blocks = (n_rays + rays_per_block - 1) / rays_per_block;

    raymarch_kernel<<<blocks, THREADS>>>(r, pivot, W1, b1, W2, b2, n_it,
                                         (float*)d_out, n_rays);
}

// round 15
// speedup vs baseline: 1.0976x; 1.0976x over previous
#include <cuda_runtime.h>

#define HIDDEN 128
#define NCACHE 96          // hidden units with per-ray u_j cached in smem
#define THREADS 256
#define RPT 2              // rays per thread = one packed f32x2 pair

typedef unsigned long long ull;

__device__ __forceinline__ float ex2f_(float x) {
    float y; asm("ex2.approx.f32 %0, %1;" : "=f"(y) : "f"(x)); return y;
}
__device__ __forceinline__ ull pk2(float lo, float hi) {
    ull r; asm("mov.b64 %0, {%1, %2};" : "=l"(r) : "f"(lo), "f"(hi)); return r;
}
__device__ __forceinline__ void upk2(ull v, float& lo, float& hi) {
    asm("mov.b64 {%0, %1}, %2;" : "=f"(lo), "=f"(hi) : "l"(v));
}
__device__ __forceinline__ ull ffma2(ull a, ull b, ull c) {
    ull d; asm("fma.rn.f32x2 %0, %1, %2, %3;" : "=l"(d) : "l"(a), "l"(b), "l"(c)); return d;
}
__device__ __forceinline__ ull fmul2(ull a, ull b) {
    ull d; asm("mul.rn.f32x2 %0, %1, %2;" : "=l"(d) : "l"(a), "l"(b)); return d;
}
__device__ __forceinline__ ull abs2_(ull a) {
    ull d; asm("and.b64 %0, %1, 0x7FFFFFFF7FFFFFFF;" : "=l"(d) : "l"(a)); return d;
}

// Degree-3 poly for ln(1+e), e in [0,1] (verified R7; max err ~5.1e-4,
// end-to-end rel_err ~1e-5). c0 folded into the global linear constant.
#define PE0  0.0005089380f
#define PE1  0.9823484000f
#define PE2 -0.3970146000f
#define PE3  0.1076817600f

struct __align__(16) W48 {
    ull w0, w1, w2, b;    // W1 rows + b1, pre-scaled by log2(e), dup {w,w}
    ull w2p;              // {W2, W2}
    ull pad;
};

// Dynamic smem layout:
//   [0, 6144)            W48 s_w[128]
//   [6144, 7680)         ulonglong2 s_cw[96]   ({c_dup, w2_dup})
//   [7680, 7696)         float s_lin[4]
//   [7696, 204304)       ull s_u[96*256]       (per-thread u_j cache)
#define SMEM_W    0
#define SMEM_CW   6144
#define SMEM_LIN  7680
#define SMEM_U    7696
#define SMEM_TOTAL (SMEM_U + NCACHE * THREADS * 8)

__global__ __launch_bounds__(THREADS)
void raymarch_kernel(const float* __restrict__ r,
                     const float* __restrict__ pivot,
                     const float* __restrict__ W1,
                     const float* __restrict__ b1,
                     const float* __restrict__ W2,
                     const float* __restrict__ b2,
                     const int*   __restrict__ n_iter_p,
                     float* __restrict__ out,
                     int n_rays)
{
    extern __shared__ char smem_raw[];
    W48*        s_w   = reinterpret_cast<W48*>(smem_raw + SMEM_W);
    ulonglong2* s_cw  = reinterpret_cast<ulonglong2*>(smem_raw + SMEM_CW);
    float*      s_lin = reinterpret_cast<float*>(smem_raw + SMEM_LIN);
    ull*        s_u   = reinterpret_cast<ull*>(smem_raw + SMEM_U);

    const float L2E = 1.4426950408889634f;
    const float LN2 = 0.6931471805599453f;

    const int tid = threadIdx.x;
    const float pv0 = pivot[0], pv1 = pivot[1], pv2 = pivot[2];

    if (tid < HIDDEN) {
        float a0 = W1[tid] * L2E;
        float a1 = W1[HIDDEN + tid] * L2E;
        float a2 = W1[2 * HIDDEN + tid] * L2E;
        float bb = b1[tid] * L2E;
        float w2 = W2[tid];
        s_w[tid].w0  = pk2(a0, a0);
        s_w[tid].w1  = pk2(a1, a1);
        s_w[tid].w2  = pk2(a2, a2);
        s_w[tid].b   = pk2(bb, bb);
        s_w[tid].w2p = pk2(w2, w2);
        s_w[tid].pad = 0ull;
        if (tid < NCACHE) {
            // c_j = (w_j . pivot + b1_j) * log2e
            float c = fmaf(a0, pv0, fmaf(a1, pv1, fmaf(a2, pv2, bb)));
            s_cw[tid].x = pk2(c, c);
            s_cw[tid].y = pk2(w2, w2);
        }
    }
    // Warp 0: reduce v = sum_j W2_j*W1_j, cb = sum_j W2_j*b1_j, sw = sum W2_j.
    if (tid < 32) {
        float vx = 0.f, vy = 0.f, vz = 0.f, cb = 0.f, sw = 0.f;
        #pragma unroll
        for (int k = 0; k < 4; ++k) {
            int j = tid + 32 * k;
            float w2 = W2[j];
            vx = fmaf(w2, W1[j], vx);
            vy = fmaf(w2, W1[HIDDEN + j], vy);
            vz = fmaf(w2, W1[2 * HIDDEN + j], vz);
            cb = fmaf(w2, b1[j], cb);
            sw += w2;
        }
        #pragma unroll
        for (int o = 16; o > 0; o >>= 1) {
            vx += __shfl_xor_sync(0xFFFFFFFF, vx, o);
            vy += __shfl_xor_sync(0xFFFFFFFF, vy, o);
            vz += __shfl_xor_sync(0xFFFFFFFF, vz, o);
            cb += __shfl_xor_sync(0xFFFFFFFF, cb, o);
            sw += __shfl_xor_sync(0xFFFFFFFF, sw, o);
        }
        if (tid == 0) {
            s_lin[0] = 0.5f * vx;
            s_lin[1] = 0.5f * vy;
            s_lin[2] = 0.5f * vz;
            s_lin[3] = 0.5f * cb + b2[0] + PE0 * sw;
        }
    }
    __syncthreads();

    const float lx = s_lin[0], ly = s_lin[1], lz = s_lin[2], lw = s_lin[3];
    const float linA = fmaf(lx, pv0, fmaf(ly, pv1, fmaf(lz, pv2, lw)));
    const int n_it = n_iter_p ? *n_iter_p : 20;

    const int base = (blockIdx.x * THREADS + tid) * RPT;
    const bool valid = (base + 1 < n_rays);

    float4 rv0 = valid ? reinterpret_cast<const float4*>(r)[base]
                       : make_float4(1.f, 0.f, 0.f, 0.f);
    float4 rv1 = valid ? reinterpret_cast<const float4*>(r)[base + 1]
                       : make_float4(1.f, 0.f, 0.f, 0.f);

    float inv0 = rsqrtf(rv0.x * rv0.x + rv0.y * rv0.y + rv0.z * rv0.z + rv0.w * rv0.w);
    float inv1 = rsqrtf(rv1.x * rv1.x + rv1.y * rv1.y + rv1.z * rv1.z + rv1.w * rv1.w);
    float rn0_0 = rv0.x * inv0, dx0 = rv0.y * inv0, dy0 = rv0.z * inv0, dz0 = rv0.w * inv0;
    float rn0_1 = rv1.x * inv1, dx1 = rv1.y * inv1, dy1 = rv1.z * inv1, dz1 = rv1.w * inv1;

    float linB0 = fmaf(lz, dz0, fmaf(ly, dy0, lx * dx0));
    float linB1 = fmaf(lz, dz1, fmaf(ly, dy1, lx * dx1));

    // Precompute per-ray u_j = (w_j . d) * log2e for cached j, into smem.
    // Each thread writes/reads only its own slots -> no barrier needed.
    #pragma unroll 4
    for (int j = 0; j < NCACHE; ++j) {
        float a0l, a0h, a1l, a1h, a2l, a2h;
        upk2(s_w[j].w0, a0l, a0h);
        upk2(s_w[j].w1, a1l, a1h);
        upk2(s_w[j].w2, a2l, a2h);
        float u0 = fmaf(a0l, dx0, fmaf(a1l, dy0, a2l * dz0));
        float u1 = fmaf(a0l, dx1, fmaf(a1l, dy1, a2l * dz1));
        s_u[j * THREADS + tid] = pk2(u0, u1);
    }

    float alpha0 = 0.f, alpha1 = 0.f;

    const ull C1 = pk2(PE1, PE1), C2 = pk2(PE2, PE2), C3 = pk2(PE3, PE3);
    const ull LN2H = pk2(0.5f * LN2, 0.5f * LN2);

    for (int it = 0; it < n_it; ++it) {
        ull alphaP = pk2(alpha0, alpha1);
        float lin0 = fmaf(alpha0, linB0, linA);
        float lin1 = fmaf(alpha1, linB1, linA);
        float x0_0 = alpha0 * rn0_0;
        float x0_1 = alpha1 * rn0_1;

        ull acc = 0ull;   // sum_j W2 * (poly*e + ln2/2*|aL|)

        // Cached hidden units: arg = c_j + alpha * u_j  (1 FFMA2)
        #pragma unroll 4
        for (int j = 0; j < NCACHE; ++j) {
            ull uj = s_u[j * THREADS + tid];
            ulonglong2 cw = s_cw[j];

            ull aL = ffma2(alphaP, uj, cw.x);
            ull ab = abs2_(aL);
            float alo, ahi; upk2(ab, alo, ahi);
            float elo = ex2f_(-alo);
            float ehi = ex2f_(-ahi);
            ull e2 = pk2(elo, ehi);

            ull p = ffma2(C3, e2, C2);
            p = ffma2(p, e2, C1);
            ull t = fmul2(p, e2);
            ull z = ffma2(LN2H, ab, t);
            acc = ffma2(cw.y, z, acc);
        }

        // Uncached tail: classic 3-FMA arg
        ull p0d = pk2(fmaf(alpha0, dx0, pv0), fmaf(alpha1, dx1, pv0));
        ull p1d = pk2(fmaf(alpha0, dy0, pv1), fmaf(alpha1, dy1, pv1));
        ull p2d = pk2(fmaf(alpha0, dz0, pv2), fmaf(alpha1, dz1, pv2));

        #pragma unroll 4
        for (int j = NCACHE; j < HIDDEN; ++j) {
            ulonglong2 q0 = *reinterpret_cast<const ulonglong2*>(&s_w[j].w0);
            ulonglong2 q1 = *reinterpret_cast<const ulonglong2*>(&s_w[j].w2);
            ull w2p = s_w[j].w2p;

            ull aL = ffma2(p0d, q0.x, ffma2(p1d, q0.y, ffma2(p2d, q1.x, q1.y)));
            ull ab = abs2_(aL);
            float alo, ahi; upk2(ab, alo, ahi);
            float elo = ex2f_(-alo);
            float ehi = ex2f_(-ahi);
            ull e2 = pk2(elo, ehi);

            ull p = ffma2(C3, e2, C2);
            p = ffma2(p, e2, C1);
            ull t = fmul2(p, e2);
            ull z = ffma2(LN2H, ab, t);
            acc = ffma2(w2p, z, acc);
        }

        float pl, ph; upk2(acc, pl, ph);
        float s0 = pl + lin0;
        float s1 = ph + lin1;

        float a0 = fabsf(s0);
        float a1 = fabsf(s1);
        float ext0 = fmaxf(fmaxf(s0, x0_0 - a0), -a0 - x0_0);
        float ext1 = fmaxf(fmaxf(s1, x0_1 - a1), -a1 - x0_1);
        alpha0 -= ext0;
        alpha1 -= ext1;
    }

    if (valid) {
        out[3 * base + 0] = fmaf(alpha0, dx0, pv0);
        out[3 * base + 1] = fmaf(alpha0, dy0, pv1);
        out[3 * base + 2] = fmaf(alpha0, dz0, pv2);
        out[3 * base + 3] = fmaf(alpha1, dx1, pv0);
        out[3 * base + 4] = fmaf(alpha1, dy1, pv1);
        out[3 * base + 5] = fmaf(alpha1, dz1, pv2);
    }
}

extern "C" void kernel_launch(void* const* d_in, const int* in_sizes, int n_in,
                              void* d_out, int out_size)
{
    const float* r     = (const float*)d_in[0];
    const float* pivot = (const float*)d_in[1];
    const float* W1    = (const float*)d_in[2];
    const float* b1    = (const float*)d_in[3];
    const float* W2    = (const float*)d_in[4];
    const float* b2    = (const float*)d_in[5];
    const int*   n_it  = (n_in > 6) ? (const int*)d_in[6] : nullptr;

    // One-time attribute set (first call is the correctness run, pre-capture).
    static cudaError_t attr_rc = cudaFuncSetAttribute(
        raymarch_kernel, cudaFuncAttributeMaxDynamicSharedMemorySize, SMEM_TOTAL);
    (void)attr_rc;

    const int n_rays = in_sizes[0] / 4;
    const int rays_per_block = THREADS * RPT;
    const int blocks = (n_rays + rays_per_block - 1) / rays_per_block;

    raymarch_kernel<<<blocks, THREADS, SMEM_TOTAL>>>(r, pivot, W1, b1, W2, b2,
                                                     n_it, (float*)d_out, n_rays);
}

// round 16
// speedup vs baseline: 1.2505x; 1.1393x over previous
#include <cuda_runtime.h>

#define HIDDEN 128
#define THREADS 64
#define NRAY 4    // rays per thread = 2 packed f32x2 pairs

typedef unsigned long long ull;

__device__ __forceinline__ float ex2f_(float x) {
    float y; asm("ex2.approx.f32 %0, %1;" : "=f"(y) : "f"(x)); return y;
}
__device__ __forceinline__ ull pk2(float lo, float hi) {
    ull r; asm("mov.b64 %0, {%1, %2};" : "=l"(r) : "f"(lo), "f"(hi)); return r;
}
__device__ __forceinline__ void upk2(ull v, float& lo, float& hi) {
    asm("mov.b64 {%0, %1}, %2;" : "=f"(lo), "=f"(hi) : "l"(v));
}
__device__ __forceinline__ ull ffma2(ull a, ull b, ull c) {
    ull d; asm("fma.rn.f32x2 %0, %1, %2, %3;" : "=l"(d) : "l"(a), "l"(b), "l"(c)); return d;
}
__device__ __forceinline__ ull fmul2(ull a, ull b) {
    ull d; asm("mul.rn.f32x2 %0, %1, %2;" : "=l"(d) : "l"(a), "l"(b)); return d;
}
__device__ __forceinline__ ull abs2_(ull a) {
    ull d; asm("and.b64 %0, %1, 0x7FFFFFFF7FFFFFFF;" : "=l"(d) : "l"(a)); return d;
}

// Degree-3 poly for ln(1+e), e in [0,1] (verified R7; max err ~5.1e-4,
// end-to-end rel_err ~1e-5). c0 folded into the global constant term.
#define PE0  0.0005089380f
#define PE1  0.9823484000f
#define PE2 -0.3970146000f
#define PE3  0.1076817600f

struct __align__(16) W48 {
    ull w0, w1, w2, b;    // W1 rows + b1, pre-scaled by log2(e), dup {w,w}
    ull w2p;              // {W2, W2}
    ull w2h;              // {W2*ln2/2, W2*ln2/2}
};

__global__ __launch_bounds__(THREADS, 14)
void raymarch_kernel(const float* __restrict__ r,
                     const float* __restrict__ pivot,
                     const float* __restrict__ W1,
                     const float* __restrict__ b1,
                     const float* __restrict__ W2,
                     const float* __restrict__ b2,
                     const int*   __restrict__ n_iter_p,
                     float* __restrict__ out,
                     int n_rays)
{
    __shared__ W48 s_w[HIDDEN];     // 6 KB
    __shared__ float s_lin[4];      // {vx/2, vy/2, vz/2, const term}

    const float L2E = 1.4426950408889634f;
    const float LN2 = 0.6931471805599453f;

    const int tid = threadIdx.x;
    // 64 threads -> each initializes 2 hidden units.
    #pragma unroll
    for (int h = 0; h < 2; ++h) {
        int j = tid + h * THREADS;
        float a0 = W1[j] * L2E;
        float a1 = W1[HIDDEN + j] * L2E;
        float a2 = W1[2 * HIDDEN + j] * L2E;
        float bb = b1[j] * L2E;
        float w2 = W2[j];
        s_w[j].w0  = pk2(a0, a0);
        s_w[j].w1  = pk2(a1, a1);
        s_w[j].w2  = pk2(a2, a2);
        s_w[j].b   = pk2(bb, bb);
        s_w[j].w2p = pk2(w2, w2);
        float wh = w2 * (0.5f * LN2);
        s_w[j].w2h = pk2(wh, wh);
    }
    // Warp 0: reduce v = sum_j W2_j*W1_j, cb = sum_j W2_j*b1_j, sw = sum W2_j.
    if (tid < 32) {
        float vx = 0.f, vy = 0.f, vz = 0.f, cb = 0.f, sw = 0.f;
        #pragma unroll
        for (int k = 0; k < 4; ++k) {
            int j = tid + 32 * k;
            float w2 = W2[j];
            vx = fmaf(w2, W1[j], vx);
            vy = fmaf(w2, W1[HIDDEN + j], vy);
            vz = fmaf(w2, W1[2 * HIDDEN + j], vz);
            cb = fmaf(w2, b1[j], cb);
            sw += w2;
        }
        #pragma unroll
        for (int o = 16; o > 0; o >>= 1) {
            vx += __shfl_xor_sync(0xFFFFFFFF, vx, o);
            vy += __shfl_xor_sync(0xFFFFFFFF, vy, o);
            vz += __shfl_xor_sync(0xFFFFFFFF, vz, o);
            cb += __shfl_xor_sync(0xFFFFFFFF, cb, o);
            sw += __shfl_xor_sync(0xFFFFFFFF, sw, o);
        }
        if (tid == 0) {
            s_lin[0] = 0.5f * vx;
            s_lin[1] = 0.5f * vy;
            s_lin[2] = 0.5f * vz;
            s_lin[3] = 0.5f * cb + b2[0] + PE0 * sw;
        }
    }
    __syncthreads();

    const float pv0 = pivot[0], pv1 = pivot[1], pv2 = pivot[2];
    const float lx = s_lin[0], ly = s_lin[1], lz = s_lin[2], lw = s_lin[3];
    const int n_it = n_iter_p ? *n_iter_p : 20;

    const int base = (blockIdx.x * THREADS + tid) * NRAY;
    const bool valid = (base + NRAY - 1 < n_rays);

    float rn0[NRAY], dx[NRAY], dy[NRAY], dz[NRAY], alpha[NRAY];
    #pragma unroll
    for (int k = 0; k < NRAY; ++k) {
        float4 rv = valid ? reinterpret_cast<const float4*>(r)[base + k]
                          : make_float4(1.f, 0.f, 0.f, 0.f);
        float inv = rsqrtf(rv.x * rv.x + rv.y * rv.y + rv.z * rv.z + rv.w * rv.w);
        rn0[k] = rv.x * inv;
        dx[k] = rv.y * inv;
        dy[k] = rv.z * inv;
        dz[k] = rv.w * inv;
        alpha[k] = 0.f;
    }

    const ull C1 = pk2(PE1, PE1), C2 = pk2(PE2, PE2), C3 = pk2(PE3, PE3);

    for (int it = 0; it < n_it; ++it) {
        ull p0d[2], p1d[2], p2d[2], accP[2], accM[2];
        float lin[NRAY], x0[NRAY];

        #pragma unroll
        for (int q = 0; q < 2; ++q) {
            const int k = 2 * q;
            float pa0 = fmaf(alpha[k],   dx[k],   pv0);
            float pb0 = fmaf(alpha[k+1], dx[k+1], pv0);
            float pa1 = fmaf(alpha[k],   dy[k],   pv1);
            float pb1 = fmaf(alpha[k+1], dy[k+1], pv1);
            float pa2 = fmaf(alpha[k],   dz[k],   pv2);
            float pb2 = fmaf(alpha[k+1], dz[k+1], pv2);
            p0d[q] = pk2(pa0, pb0);
            p1d[q] = pk2(pa1, pb1);
            p2d[q] = pk2(pa2, pb2);
            // linear (relu mean) term, exact: 0.5*(v.p) + const
            lin[k]   = fmaf(lz, pa2, fmaf(ly, pa1, fmaf(lx, pa0, lw)));
            lin[k+1] = fmaf(lz, pb2, fmaf(ly, pb1, fmaf(lx, pb0, lw)));
            x0[k]   = alpha[k]   * rn0[k];
            x0[k+1] = alpha[k+1] * rn0[k+1];
            accP[q] = 0ull;
            accM[q] = 0ull;
        }

        #pragma unroll 4
        for (int j = 0; j < HIDDEN; ++j) {
            ulonglong2 q0 = *reinterpret_cast<const ulonglong2*>(&s_w[j].w0);   // w0, w1
            ulonglong2 q1 = *reinterpret_cast<const ulonglong2*>(&s_w[j].w2);   // w2, b
            ulonglong2 q2 = *reinterpret_cast<const ulonglong2*>(&s_w[j].w2p);  // w2p, w2h

            #pragma unroll
            for (int q = 0; q < 2; ++q) {
                // aL = (x . W1 + b1) * log2e, packed over 2 rays
                ull aL = ffma2(p0d[q], q0.x, ffma2(p1d[q], q0.y, ffma2(p2d[q], q1.x, q1.y)));
                ull ab = abs2_(aL);
                float alo, ahi; upk2(ab, alo, ahi);

                // e = 2^(-|aL|)
                float elo = ex2f_(-alo);
                float ehi = ex2f_(-ahi);
                ull e2 = pk2(elo, ehi);

                // ln(1+e) minus c0: Horner (c0 folded into lw)
                ull p = ffma2(C3, e2, C2);
                p = ffma2(p, e2, C1);
                ull t = fmul2(p, e2);

                accP[q] = ffma2(q2.x, t, accP[q]);   // W2 * (poly*e)
                accM[q] = ffma2(q2.y, ab, accM[q]);  // (W2*ln2/2) * |aL|
            }
        }

        #pragma unroll
        for (int q = 0; q < 2; ++q) {
            const int k = 2 * q;
            float pl, ph, ml, mh;
            upk2(accP[q], pl, ph);
            upk2(accM[q], ml, mh);
            float s0 = (pl + ml) + lin[k];
            float s1 = (ph + mh) + lin[k+1];
            float a0 = fabsf(s0);
            float a1 = fabsf(s1);
            float ext0 = fmaxf(fmaxf(s0, x0[k]   - a0), -a0 - x0[k]);
            float ext1 = fmaxf(fmaxf(s1, x0[k+1] - a1), -a1 - x0[k+1]);
            alpha[k]   -= ext0;
            alpha[k+1] -= ext1;
        }
    }

    if (valid) {
        #pragma unroll
        for (int k = 0; k < NRAY; ++k) {
            const int i = base + k;
            out[3 * i + 0] = fmaf(alpha[k], dx[k], pv0);
            out[3 * i + 1] = fmaf(alpha[k], dy[k], pv1);
            out[3 * i + 2] = fmaf(alpha[k], dz[k], pv2);
        }
    }
}

extern "C" void kernel_launch(void* const* d_in, const int* in_sizes, int n_in,
                              void* d_out, int out_size)
{
    const float* r     = (const float*)d_in[0];
    const float* pivot = (const float*)d_in[1];
    const float* W1    = (const float*)d_in[2];
    const float* b1    = (const float*)d_in[3];
    const float* W2    = (const float*)d_in[4];
    const float* b2    = (const float*)d_in[5];
    const int*   n_it  = (n_in > 6) ? (const int*)d_in[6] : nullptr;

    const int n_rays = in_sizes[0] / 4;
    const int rays_per_block = THREADS * NRAY;
    const int blocks = (n_rays + rays_per_block - 1) / rays_per_block;

    raymarch_kernel<<<blocks, THREADS>>>(r, pivot, W1, b1, W2, b2, n_it,
                                         (float*)d_out, n_rays);
}

// round 17
// speedup vs baseline: 1.2861x; 1.0284x over previous
#include <cuda_runtime.h>

#define HIDDEN 128
#define THREADS 64
#define NRAY 4    // rays per thread = 2 packed f32x2 pairs

typedef unsigned long long ull;

__device__ __forceinline__ float ex2f_(float x) {
    float y; asm("ex2.approx.f32 %0, %1;" : "=f"(y) : "f"(x)); return y;
}
__device__ __forceinline__ ull pk2(float lo, float hi) {
    ull r; asm("mov.b64 %0, {%1, %2};" : "=l"(r) : "f"(lo), "f"(hi)); return r;
}
__device__ __forceinline__ void upk2(ull v, float& lo, float& hi) {
    asm("mov.b64 {%0, %1}, %2;" : "=f"(lo), "=f"(hi) : "l"(v));
}
__device__ __forceinline__ ull ffma2(ull a, ull b, ull c) {
    ull d; asm("fma.rn.f32x2 %0, %1, %2, %3;" : "=l"(d) : "l"(a), "l"(b), "l"(c)); return d;
}
__device__ __forceinline__ ull fmul2(ull a, ull b) {
    ull d; asm("mul.rn.f32x2 %0, %1, %2;" : "=l"(d) : "l"(a), "l"(b)); return d;
}
__device__ __forceinline__ ull abs2_(ull a) {
    ull d; asm("and.b64 %0, %1, 0x7FFFFFFF7FFFFFFF;" : "=l"(d) : "l"(a)); return d;
}

// Degree-3 poly for ln(1+e), e in [0,1] (verified R7; max err ~5.1e-4,
// end-to-end rel_err ~1e-5). c0 folded into the global constant term.
#define PE0  0.0005089380f
#define PE1  0.9823484000f
#define PE2 -0.3970146000f
#define PE3  0.1076817600f

struct __align__(16) W48 {
    ull w0, w1, w2, b;    // W1 rows + b1, pre-scaled by log2(e), dup {w,w}
    ull w2p;              // {W2, W2}
    ull w2h;              // {W2*ln2/2, W2*ln2/2}
};

__global__ __launch_bounds__(THREADS, 14)
void raymarch_kernel(const float* __restrict__ r,
                     const float* __restrict__ pivot,
                     const float* __restrict__ W1,
                     const float* __restrict__ b1,
                     const float* __restrict__ W2,
                     const float* __restrict__ b2,
                     const int*   __restrict__ n_iter_p,
                     float* __restrict__ out,
                     int n_rays)
{
    __shared__ W48 s_w[HIDDEN];     // 6 KB
    __shared__ float s_lin[4];      // {vx/2, vy/2, vz/2, const term}
    __shared__ float s_sp;          // sdf(pivot) under the same approximation

    const float L2E = 1.4426950408889634f;
    const float LN2 = 0.6931471805599453f;

    const int tid = threadIdx.x;
    const float pv0 = pivot[0], pv1 = pivot[1], pv2 = pivot[2];

    // 64 threads -> each initializes 2 hidden units.
    #pragma unroll
    for (int h = 0; h < 2; ++h) {
        int j = tid + h * THREADS;
        float a0 = W1[j] * L2E;
        float a1 = W1[HIDDEN + j] * L2E;
        float a2 = W1[2 * HIDDEN + j] * L2E;
        float bb = b1[j] * L2E;
        float w2 = W2[j];
        s_w[j].w0  = pk2(a0, a0);
        s_w[j].w1  = pk2(a1, a1);
        s_w[j].w2  = pk2(a2, a2);
        s_w[j].b   = pk2(bb, bb);
        s_w[j].w2p = pk2(w2, w2);
        float wh = w2 * (0.5f * LN2);
        s_w[j].w2h = pk2(wh, wh);
    }
    // Warp 0: reduce v = sum_j W2_j*W1_j, cb, sw, AND the nonlinear part of
    // sdf(pivot) under the same approximation the main loop uses.
    if (tid < 32) {
        float vx = 0.f, vy = 0.f, vz = 0.f, cb = 0.f, sw = 0.f;
        float nl = 0.f;   // sum_j w2*(poly(e)*e + (ln2/2)*|aL|) at x = pivot
        #pragma unroll
        for (int k = 0; k < 4; ++k) {
            int j = tid + 32 * k;
            float w2 = W2[j];
            float w1x = W1[j], w1y = W1[HIDDEN + j], w1z = W1[2 * HIDDEN + j];
            float bj = b1[j];
            vx = fmaf(w2, w1x, vx);
            vy = fmaf(w2, w1y, vy);
            vz = fmaf(w2, w1z, vz);
            cb = fmaf(w2, bj, cb);
            sw += w2;
            // aL at pivot (same scaled form as the main loop)
            float aL = (fmaf(w1x, pv0, fmaf(w1y, pv1, fmaf(w1z, pv2, bj)))) * L2E;
            float ab = fabsf(aL);
            float e  = ex2f_(-ab);
            float p  = fmaf(fmaf(PE3, e, PE2), e, PE1);
            nl = fmaf(w2, fmaf(p, e, (0.5f * LN2) * ab), nl);
        }
        #pragma unroll
        for (int o = 16; o > 0; o >>= 1) {
            vx += __shfl_xor_sync(0xFFFFFFFF, vx, o);
            vy += __shfl_xor_sync(0xFFFFFFFF, vy, o);
            vz += __shfl_xor_sync(0xFFFFFFFF, vz, o);
            cb += __shfl_xor_sync(0xFFFFFFFF, cb, o);
            sw += __shfl_xor_sync(0xFFFFFFFF, sw, o);
            nl += __shfl_xor_sync(0xFFFFFFFF, nl, o);
        }
        if (tid == 0) {
            float lx = 0.5f * vx, ly = 0.5f * vy, lz = 0.5f * vz;
            float lw = 0.5f * cb + b2[0] + PE0 * sw;
            s_lin[0] = lx;
            s_lin[1] = ly;
            s_lin[2] = lz;
            s_lin[3] = lw;
            // sdf(pivot) = nonlinear part + linear part at p = pivot
            s_sp = nl + fmaf(lz, pv2, fmaf(ly, pv1, fmaf(lx, pv0, lw)));
        }
    }
    __syncthreads();

    const float lx = s_lin[0], ly = s_lin[1], lz = s_lin[2], lw = s_lin[3];
    const int n_it = n_iter_p ? *n_iter_p : 20;
    // Iteration 0 collapses: x = pivot_ext for every ray and (since x0 = 0)
    // ext = max(s, -|s|) = s(pivot). So alpha after iter 0 = -sdf(pivot).
    const float alpha_init = (n_it > 0) ? -s_sp : 0.f;

    const int base = (blockIdx.x * THREADS + tid) * NRAY;
    const bool valid = (base + NRAY - 1 < n_rays);

    float rn0[NRAY], dx[NRAY], dy[NRAY], dz[NRAY], alpha[NRAY];
    #pragma unroll
    for (int k = 0; k < NRAY; ++k) {
        float4 rv = valid ? reinterpret_cast<const float4*>(r)[base + k]
                          : make_float4(1.f, 0.f, 0.f, 0.f);
        float inv = rsqrtf(rv.x * rv.x + rv.y * rv.y + rv.z * rv.z + rv.w * rv.w);
        rn0[k] = rv.x * inv;
        dx[k] = rv.y * inv;
        dy[k] = rv.z * inv;
        dz[k] = rv.w * inv;
        alpha[k] = alpha_init;
    }

    const ull C1 = pk2(PE1, PE1), C2 = pk2(PE2, PE2), C3 = pk2(PE3, PE3);

    for (int it = 1; it < n_it; ++it) {
        ull p0d[2], p1d[2], p2d[2], accP[2], accM[2];
        float lin[NRAY], x0[NRAY];

        #pragma unroll
        for (int q = 0; q < 2; ++q) {
            const int k = 2 * q;
            float pa0 = fmaf(alpha[k],   dx[k],   pv0);
            float pb0 = fmaf(alpha[k+1], dx[k+1], pv0);
            float pa1 = fmaf(alpha[k],   dy[k],   pv1);
            float pb1 = fmaf(alpha[k+1], dy[k+1], pv1);
            float pa2 = fmaf(alpha[k],   dz[k],   pv2);
            float pb2 = fmaf(alpha[k+1], dz[k+1], pv2);
            p0d[q] = pk2(pa0, pb0);
            p1d[q] = pk2(pa1, pb1);
            p2d[q] = pk2(pa2, pb2);
            // linear (relu mean) term, exact: 0.5*(v.p) + const
            lin[k]   = fmaf(lz, pa2, fmaf(ly, pa1, fmaf(lx, pa0, lw)));
            lin[k+1] = fmaf(lz, pb2, fmaf(ly, pb1, fmaf(lx, pb0, lw)));
            x0[k]   = alpha[k]   * rn0[k];
            x0[k+1] = alpha[k+1] * rn0[k+1];
            accP[q] = 0ull;
            accM[q] = 0ull;
        }

        #pragma unroll 4
        for (int j = 0; j < HIDDEN; ++j) {
            ulonglong2 q0 = *reinterpret_cast<const ulonglong2*>(&s_w[j].w0);   // w0, w1
            ulonglong2 q1 = *reinterpret_cast<const ulonglong2*>(&s_w[j].w2);   // w2, b
            ulonglong2 q2 = *reinterpret_cast<const ulonglong2*>(&s_w[j].w2p);  // w2p, w2h

            #pragma unroll
            for (int q = 0; q < 2; ++q) {
                // aL = (x . W1 + b1) * log2e, packed over 2 rays
                ull aL = ffma2(p0d[q], q0.x, ffma2(p1d[q], q0.y, ffma2(p2d[q], q1.x, q1.y)));
                ull ab = abs2_(aL);
                float alo, ahi; upk2(ab, alo, ahi);

                // e = 2^(-|aL|)
                float elo = ex2f_(-alo);
                float ehi = ex2f_(-ahi);
                ull e2 = pk2(elo, ehi);

                // ln(1+e) minus c0: Horner (c0 folded into lw)
                ull p = ffma2(C3, e2, C2);
                p = ffma2(p, e2, C1);
                ull t = fmul2(p, e2);

                accP[q] = ffma2(q2.x, t, accP[q]);   // W2 * (poly*e)
                accM[q] = ffma2(q2.y, ab, accM[q]);  // (W2*ln2/2) * |aL|
            }
        }

        #pragma unroll
        for (int q = 0; q < 2; ++q) {
            const int k = 2 * q;
            float pl, ph, ml, mh;
            upk2(accP[q], pl, ph);
            upk2(accM[q], ml, mh);
            float s0 = (pl + ml) + lin[k];
            float s1 = (ph + mh) + lin[k+1];
            float a0 = fabsf(s0);
            float a1 = fabsf(s1);
            float ext0 = fmaxf(fmaxf(s0, x0[k]   - a0), -a0 - x0[k]);
            float ext1 = fmaxf(fmaxf(s1, x0[k+1] - a1), -a1 - x0[k+1]);
            alpha[k]   -= ext0;
            alpha[k+1] -= ext1;
        }
    }

    if (valid) {
        #pragma unroll
        for (int k = 0; k < NRAY; ++k) {
            const int i = base + k;
            out[3 * i + 0] = fmaf(alpha[k], dx[k], pv0);
            out[3 * i + 1] = fmaf(alpha[k], dy[k], pv1);
            out[3 * i + 2] = fmaf(alpha[k], dz[k], pv2);
        }
    }
}

extern "C" void kernel_launch(void* const* d_in, const int* in_sizes, int n_in,
                              void* d_out, int out_size)
{
    const float* r     = (const float*)d_in[0];
    const float* pivot = (const float*)d_in[1];
    const float* W1    = (const float*)d_in[2];
    const float* b1    = (const float*)d_in[3];
    const float* W2    = (const float*)d_in[4];
    const float* b2    = (const float*)d_in[5];
    const int*   n_it  = (n_in > 6) ? (const int*)d_in[6] : nullptr;

    const int n_rays = in_sizes[0] / 4;
    const int rays_per_block = THREADS * NRAY;
    const int blocks = (n_rays + rays_per_block - 1) / rays_per_block;

    raymarch_kernel<<<blocks, THREADS>>>(r, pivot, W1, b1, W2, b2, n_it,
                                         (float*)d_out, n_rays);
}